// round 10
// baseline (speedup 1.0000x reference)
#include <cuda_runtime.h>
#include <cuda_bf16.h>

#define NBX 512
#define NBY 512
#define KK  5
#define TARGET_AREA 0.9f
#define MS  520                     // padded map row stride (floats)
#define MAPSZ (512 * MS + 16)

#define SPLIT_XF 354.0f             // node split: x < 354 -> A (sx0 <= 351)
#define XTILES_L 11                 // finishL: cells x in [0, 352)
#define XTILES_R 5                  // finishR: cells x in [352, 512)
#define GRID_B   296               // persistent scatterB (2 blocks/SM x 148)

// ---- static device scratch (no runtime allocation allowed) ----
// M copies: cell (x,y) at idx x*MS + (y - k) + 4   (copy k)
// T copies: cell (x,y) at idx y*MS + (x - k) + 4   (copy k, transposed)
__device__ __align__(16) float g_M[4][MAPSZ];
__device__ __align__(16) float g_T[4][MAPSZ];
__device__ float g_sum;             // reset by finishR's last block
__device__ int   g_done;

__device__ __forceinline__ void red_add_v4(float* a, float v0, float v1, float v2, float v3) {
    asm volatile("red.global.add.v4.f32 [%0], {%1, %2, %3, %4};"
                 :: "l"(a), "f"(v0), "f"(v1), "f"(v2), "f"(v3) : "memory");
}
__device__ __forceinline__ void red_add_f(float* a, float v) {
    asm volatile("red.global.add.f32 [%0], %1;" :: "l"(a), "f"(v) : "memory");
}

__device__ __forceinline__ void pot5(float coord, float s, int s0, float* p) {
    float ctr = coord + 0.5f * s;
    float a   = 4.0f / ((s + 2.0f) * (s + 4.0f));
    float cb  = s * (2.0f / (s + 4.0f));
    float p1  = 0.5f * s + 1.0f;
    float p2  = 0.5f * s + 2.0f;
    float d0  = ctr - ((float)s0 + 0.5f);
#pragma unroll
    for (int k = 0; k < KK; k++) {
        float d = fabsf(d0 - (float)k);
        float v;
        if (d < p1)      v = s * (1.0f - a * d * d);
        else if (d < p2) { float t = d - p2; v = cb * t * t; }
        else             v = 0.0f;
        p[k] = v;
    }
}

__device__ __forceinline__ int strip5(float* q) {
    int sft = 0;
#pragma unroll
    for (int t = 0; t < 4; t++) {
        if (q[0] == 0.0f) {
            q[0] = q[1]; q[1] = q[2]; q[2] = q[3]; q[3] = q[4]; q[4] = 0.0f;
            sft++;
        }
    }
    return sft;
}

// Per-node deposit: <=5 row-v4 REDs + (P=.5) column T-v4 + (P~.125) corner
__device__ __forceinline__ void deposit_node(float x, float y, float sx, float sy, int n) {
    int sx0 = min(max((int)floorf(x - 2.0f), 0), NBX - KK);
    int sy0 = min(max((int)floorf(y - 2.0f), 0), NBY - KK);

    float px[KK], py[KK];
    pot5(x, sx, sx0, px);
    pot5(y, sy, sy0, py);

    float q[KK] = {py[0], py[1], py[2], py[3], py[4]};
    int ys = sy0 + strip5(q);
    float colv = q[4];
    float* Mk = g_M[ys & 3];
    int ycol = (ys & ~3) + 4;

#pragma unroll
    for (int r = 0; r < KK; r++) {
        float vx = px[r];
        if (vx != 0.0f)
            red_add_v4(Mk + (sx0 + r) * MS + ycol,
                       vx * q[0], vx * q[1], vx * q[2], vx * q[3]);
    }

    if (colv != 0.0f) {
        float c[KK] = {px[0], px[1], px[2], px[3], px[4]};
        int xs = sx0 + strip5(c);
        float corner = c[4];
        float* Tk = g_T[xs & 3];
        red_add_v4(Tk + (sy0 + 4) * MS + (xs & ~3) + 4,
                   colv * c[0], colv * c[1], colv * c[2], colv * c[3]);
        if (corner != 0.0f)
            red_add_f(&g_M[0][(sx0 + 4) * MS + (sy0 + 4) + 4], corner * colv);
    }
}

// ---------------------------------------------------------------------------
// scatterA: nodes with x < SPLIT_XF (writes rows <= 355 only)
// ---------------------------------------------------------------------------
__global__ void __launch_bounds__(256) scatterA_kernel(
    const float* __restrict__ pos, const float* __restrict__ sxs,
    const float* __restrict__ sys, int n)
{
    int i = blockIdx.x * blockDim.x + threadIdx.x;
    if (i >= n) return;
    float x = pos[i];
    if (x >= SPLIT_XF) return;
    deposit_node(x, pos[n + i], sxs[i], sys[i], n);
}

// ---------------------------------------------------------------------------
// scatterB: persistent grid; fires PDL trigger at entry so finishL (launched
// with programmatic stream serialization) starts concurrently. B writes only
// rows >= 352 — address-disjoint from finishL's region (cells x < 352).
// ---------------------------------------------------------------------------
__global__ void __launch_bounds__(256, 2) scatterB_kernel(
    const float* __restrict__ pos, const float* __restrict__ sxs,
    const float* __restrict__ sys, int n)
{
#if __CUDA_ARCH__ >= 900
    cudaTriggerProgrammaticLaunchCompletion();
#endif
    int gtid = blockIdx.x * 256 + threadIdx.x;
    for (int i = gtid; i < n; i += GRID_B * 256) {
        float x = pos[i];
        if (x < SPLIT_XF) continue;
        deposit_node(x, pos[n + i], sxs[i], sys[i], n);
    }
}

// ---------------------------------------------------------------------------
// finish_part: tiles [xt0, xt0+nxt) x 16 y-tiles of 32x32 cells.
// final_blocks > 0 => this launch owns the ticket (writes out + resets state).
// ---------------------------------------------------------------------------
__global__ void __launch_bounds__(1024) finish_part(
    const float* __restrict__ initial, float* __restrict__ out,
    int xt0, int nxt, int final_blocks)
{
    __shared__ float ts[32][33];
    __shared__ float sd[32];

    int b    = blockIdx.x;
    int X0   = (xt0 + (b % nxt)) << 5;
    int Y0   = (b / nxt) << 5;
    int tid  = threadIdx.x;
    int lane = tid & 31;
    int row  = tid >> 5;

    // Phase 1: fold T copies into smem (32-wide along x; loads only)
    {
        int yg = Y0 + row;
        float s = 0.0f;
#pragma unroll
        for (int k = 0; k < 4; k++)
            s += g_T[k][yg * MS + (X0 + lane - k + 4)];
        ts[row][lane] = s;
    }
    __syncthreads();

    // Phase 2: per-cell density (32-wide along y; loads only)
    float acc;
    {
        int xg = X0 + row;
        int yg = Y0 + lane;
        float v = initial[xg * NBY + yg] + ts[lane][row];
#pragma unroll
        for (int k = 0; k < 4; k++)
            v += g_M[k][xg * MS + (yg - k + 4)];
        float d = v - TARGET_AREA;
        acc = d * d;
    }

    // Phase 3: zero own region (plain streaming stores)
    {
        int yg = Y0 + row;
#pragma unroll
        for (int k = 0; k < 4; k++)
            g_T[k][yg * MS + (X0 + lane - k + 4)] = 0.0f;
        int xg = X0 + row;
#pragma unroll
        for (int k = 0; k < 4; k++)
            g_M[k][xg * MS + (Y0 + lane - k + 4)] = 0.0f;
    }

    // Block reduce + (final launch only) ticketed write / state reset
#pragma unroll
    for (int off = 16; off > 0; off >>= 1)
        acc += __shfl_xor_sync(0xFFFFFFFF, acc, off);
    if (lane == 0) sd[row] = acc;
    __syncthreads();
    if (tid < 32) {
        float v = sd[tid];
#pragma unroll
        for (int off = 16; off > 0; off >>= 1)
            v += __shfl_xor_sync(0xFFFFFFFF, v, off);
        if (tid == 0) {
            atomicAdd(&g_sum, v);
            if (final_blocks > 0) {
                __threadfence();
                int t = atomicAdd(&g_done, 1);
                if (t == final_blocks - 1) {
                    out[0]  = g_sum;
                    g_sum   = 0.0f;
                    g_done  = 0;
                }
            }
        }
    }
}

// ---------------------------------------------------------------------------
extern "C" void kernel_launch(void* const* d_in, const int* in_sizes, int n_in,
                              void* d_out, int out_size) {
    const float* pos = (const float*)d_in[0];
    const float* sx  = (const float*)d_in[1];
    const float* sy  = (const float*)d_in[2];
    const float* initial = (const float*)d_in[11];
    float* out = (float*)d_out;
    int n = in_sizes[1];

    // 1) scatterA: all nodes touching cells x < 352
    scatterA_kernel<<<(n + 255) / 256, 256>>>(pos, sx, sy, n);

    // 2) scatterB: persistent; triggers PDL release immediately
    scatterB_kernel<<<GRID_B, 256>>>(pos, sx, sy, n);

    // 3) finishL: PDL launch — overlaps scatterB (disjoint region, only needs A)
    {
        cudaLaunchConfig_t cfg = {};
        cfg.gridDim  = dim3(XTILES_L * 16, 1, 1);
        cfg.blockDim = dim3(1024, 1, 1);
        cfg.dynamicSmemBytes = 0;
        cfg.stream = 0;
        cudaLaunchAttribute attr[1];
        attr[0].id = cudaLaunchAttributeProgrammaticStreamSerialization;
        attr[0].val.programmaticStreamSerializationAllowed = 1;
        cfg.attrs = attr;
        cfg.numAttrs = 1;
        cudaLaunchKernelEx(&cfg, finish_part, initial, out, 0, (int)XTILES_L, 0);
    }

    // 4) finishR: normal launch — waits for scatterB AND finishL; owns ticket
    finish_part<<<XTILES_R * 16, 1024>>>(initial, out, XTILES_L, XTILES_R,
                                         XTILES_R * 16);
}

// round 11
// speedup vs baseline: 1.2968x; 1.2968x over previous
#include <cuda_runtime.h>
#include <cuda_bf16.h>

#define NBX 512
#define NBY 512
#define KK  5
#define TARGET_AREA 0.9f
#define MS  520                     // padded map row stride (floats)
#define MAPSZ (512 * MS + 16)       // max used idx 511*520+515

// ---- static device scratch (no runtime allocation allowed) ----
// M copies: logical (x,y) stored at idx x*MS + (y - k) + 4   (copy k)
// T copies: logical (x,y) stored at idx y*MS + (x - k) + 4   (copy k, transposed)
__device__ __align__(16) float g_M[4][MAPSZ];
__device__ __align__(16) float g_T[4][MAPSZ];
__device__ float g_sum;             // reset by finish's last block
__device__ int   g_done;

__device__ __forceinline__ void red_add_v4(float* a, float v0, float v1, float v2, float v3) {
    asm volatile("red.global.add.v4.f32 [%0], {%1, %2, %3, %4};"
                 :: "l"(a), "f"(v0), "f"(v1), "f"(v2), "f"(v3) : "memory");
}
__device__ __forceinline__ void red_add_f(float* a, float v) {
    asm volatile("red.global.add.f32 [%0], %1;" :: "l"(a), "f"(v) : "memory");
}

// 5 bell-potential values over window starting at s0 (zeros only at the ends)
__device__ __forceinline__ void pot5(float coord, float s, int s0, float* p) {
    float ctr = coord + 0.5f * s;
    float a   = 4.0f / ((s + 2.0f) * (s + 4.0f));
    float cb  = s * (2.0f / (s + 4.0f));
    float p1  = 0.5f * s + 1.0f;
    float p2  = 0.5f * s + 2.0f;
    float d0  = ctr - ((float)s0 + 0.5f);
#pragma unroll
    for (int k = 0; k < KK; k++) {
        float d = fabsf(d0 - (float)k);
        float v;
        if (d < p1)      v = s * (1.0f - a * d * d);
        else if (d < p2) { float t = d - p2; v = cb * t * t; }
        else             v = 0.0f;
        p[k] = v;
    }
}

// strip leading zeros from q[0..4] (shifting zeros in at the top); returns shift
__device__ __forceinline__ int strip5(float* q) {
    int sft = 0;
#pragma unroll
    for (int t = 0; t < 4; t++) {
        if (q[0] == 0.0f) {
            q[0] = q[1]; q[1] = q[2]; q[2] = q[3]; q[3] = q[4]; q[4] = 0.0f;
            sft++;
        }
    }
    return sft;
}

// ---------------------------------------------------------------------------
// Scatter: per node, <=5 row-v4 REDs + (P=.5) column T-v4 + (P~.25) corner
// (unchanged from R9 — measured at the REDG request floor)
// ---------------------------------------------------------------------------
__global__ void __launch_bounds__(256) scatter_kernel(
    const float* __restrict__ pos,
    const float* __restrict__ sxs,
    const float* __restrict__ sys,
    int n)
{
    int i = blockIdx.x * blockDim.x + threadIdx.x;
    if (i >= n) return;

    float x  = pos[i];
    float y  = pos[n + i];
    float sx = sxs[i];
    float sy = sys[i];

    int sx0 = min(max((int)floorf(x - 2.0f), 0), NBX - KK);
    int sy0 = min(max((int)floorf(y - 2.0f), 0), NBY - KK);

    float px[KK], py[KK];
    pot5(x, sx, sx0, px);
    pot5(y, sy, sy0, py);

    // strip y window; q[0..3] = v4 lanes; q[4] = leftover 5th column (0 if width<5)
    float q[KK] = {py[0], py[1], py[2], py[3], py[4]};
    int ys = sy0 + strip5(q);
    float colv = q[4];                 // nonzero only when shift==0 && width==5
    float* Mk = g_M[ys & 3];
    int ycol = (ys & ~3) + 4;          // aligned offset inside copy (ys&3)

#pragma unroll
    for (int r = 0; r < KK; r++) {
        float vx = px[r];
        if (vx != 0.0f)
            red_add_v4(Mk + (sx0 + r) * MS + ycol,
                       vx * q[0], vx * q[1], vx * q[2], vx * q[3]);
    }

    if (colv != 0.0f) {                // 5th column at logical y = sy0+4
        float c[KK] = {px[0], px[1], px[2], px[3], px[4]};
        int xs = sx0 + strip5(c);
        float corner = c[4];           // nonzero only when shift==0 && width==5
        float* Tk = g_T[xs & 3];
        red_add_v4(Tk + (sy0 + 4) * MS + (xs & ~3) + 4,
                   colv * c[0], colv * c[1], colv * c[2], colv * c[3]);
        if (corner != 0.0f)            // corner (sx0+4, sy0+4)
            red_add_f(&g_M[0][(sx0 + 4) * MS + (sy0 + 4) + 4], corner * colv);
    }
}

// ---------------------------------------------------------------------------
// Finish (R9 geometry, reordered loads): ALL 9 global loads (4 T + 4 M +
// initial) issue back-to-back BEFORE the barrier, collapsing the two L2
// latency windows into one (MLP 9). 256 blocks x 1024 threads, 32x32 tile,
// every access 32-wide coalesced. Zeroing separate, own-region only.
// ---------------------------------------------------------------------------
__global__ void __launch_bounds__(1024) finish_kernel(
    const float* __restrict__ initial,
    float* __restrict__ out)
{
    __shared__ float ts[32][33];       // stride 33: conflict-free both ways
    __shared__ float sd[32];

    int b    = blockIdx.x;
    int X0   = (b & 15) << 5;
    int Y0   = (b >> 4) << 5;
    int tid  = threadIdx.x;
    int lane = tid & 31;
    int row  = tid >> 5;               // 0..31 (warp id = local row)

    // ---- Issue ALL independent global loads first (9-deep MLP) ----
    int ygT = Y0 + row;                // T-space: coalesced along x (lane)
    float t0 = g_T[0][ygT * MS + (X0 + lane + 4)];
    float t1 = g_T[1][ygT * MS + (X0 + lane + 3)];
    float t2 = g_T[2][ygT * MS + (X0 + lane + 2)];
    float t3 = g_T[3][ygT * MS + (X0 + lane + 1)];

    int xgM = X0 + row;                // M-space: coalesced along y (lane)
    int ygM = Y0 + lane;
    float m0 = g_M[0][xgM * MS + (ygM + 4)];
    float m1 = g_M[1][xgM * MS + (ygM + 3)];
    float m2 = g_M[2][xgM * MS + (ygM + 2)];
    float m3 = g_M[3][xgM * MS + (ygM + 1)];
    float i0 = initial[xgM * NBY + ygM];

    // ---- T fold -> smem transpose ----
    ts[row][lane] = t0 + t1 + t2 + t3;
    __syncthreads();

    // ---- per-cell density + cost ----
    float v = i0 + m0 + m1 + m2 + m3 + ts[lane][row];
    float d = v - TARGET_AREA;
    float acc = d * d;

    // ---- zero own region (plain streaming stores, 32-wide) ----
    {
#pragma unroll
        for (int k = 0; k < 4; k++)
            g_T[k][ygT * MS + (X0 + lane - k + 4)] = 0.0f;
#pragma unroll
        for (int k = 0; k < 4; k++)
            g_M[k][xgM * MS + (Y0 + lane - k + 4)] = 0.0f;
    }

    // ---- block reduce (32 warps) + ticketed final write / state reset ----
#pragma unroll
    for (int off = 16; off > 0; off >>= 1)
        acc += __shfl_xor_sync(0xFFFFFFFF, acc, off);
    if (lane == 0) sd[row] = acc;
    __syncthreads();
    if (tid < 32) {
        float v2 = sd[tid];
#pragma unroll
        for (int off = 16; off > 0; off >>= 1)
            v2 += __shfl_xor_sync(0xFFFFFFFF, v2, off);
        if (tid == 0) {
            atomicAdd(&g_sum, v2);
            __threadfence();
            int t = atomicAdd(&g_done, 1);
            if (t == (int)gridDim.x - 1) {
                out[0] = g_sum;
                g_sum  = 0.0f;         // restore invariants for next replay
                g_done = 0;
            }
        }
    }
}

// ---------------------------------------------------------------------------
extern "C" void kernel_launch(void* const* d_in, const int* in_sizes, int n_in,
                              void* d_out, int out_size) {
    const float* pos = (const float*)d_in[0];
    const float* sx  = (const float*)d_in[1];
    const float* sy  = (const float*)d_in[2];
    // d_in[3..8]: ax..cy — recomputed analytically; d_in[9..10]: bin centers — analytic
    const float* initial = (const float*)d_in[11];
    float* out = (float*)d_out;

    int n = in_sizes[1];

    scatter_kernel<<<(n + 255) / 256, 256>>>(pos, sx, sy, n);
    finish_kernel<<<256, 1024>>>(initial, out);
}

// round 12
// speedup vs baseline: 1.2980x; 1.0010x over previous
#include <cuda_runtime.h>
#include <cuda_bf16.h>

#define NBX 512
#define NBY 512
#define KK  5
#define TARGET_AREA 0.9f
#define MS  520                     // padded map row stride (floats)
#define MAPSZ (512 * MS + 16)       // max used idx 511*520+515

// ---- static device scratch (no runtime allocation allowed) ----
// M copies: logical (x,y) stored at idx x*MS + (y - k) + 4   (copy k)
// T copies: logical (x,y) stored at idx y*MS + (x - k) + 4   (copy k, transposed)
__device__ __align__(16) float g_M[4][MAPSZ];
__device__ __align__(16) float g_T[4][MAPSZ];
__device__ float g_sum;             // reset by finish's last block
__device__ int   g_done;

__device__ __forceinline__ void red_add_v4(float* a, float v0, float v1, float v2, float v3) {
    asm volatile("red.global.add.v4.f32 [%0], {%1, %2, %3, %4};"
                 :: "l"(a), "f"(v0), "f"(v1), "f"(v2), "f"(v3) : "memory");
}
__device__ __forceinline__ void red_add_f(float* a, float v) {
    asm volatile("red.global.add.f32 [%0], %1;" :: "l"(a), "f"(v) : "memory");
}

// 5 bell-potential values over window starting at s0 (zeros only at the ends)
__device__ __forceinline__ void pot5(float coord, float s, int s0, float* p) {
    float ctr = coord + 0.5f * s;
    float a   = 4.0f / ((s + 2.0f) * (s + 4.0f));
    float cb  = s * (2.0f / (s + 4.0f));
    float p1  = 0.5f * s + 1.0f;
    float p2  = 0.5f * s + 2.0f;
    float d0  = ctr - ((float)s0 + 0.5f);
#pragma unroll
    for (int k = 0; k < KK; k++) {
        float d = fabsf(d0 - (float)k);
        float v;
        if (d < p1)      v = s * (1.0f - a * d * d);
        else if (d < p2) { float t = d - p2; v = cb * t * t; }
        else             v = 0.0f;
        p[k] = v;
    }
}

// strip leading zeros from q[0..4] (shifting zeros in at the top); returns shift
__device__ __forceinline__ int strip5(float* q) {
    int sft = 0;
#pragma unroll
    for (int t = 0; t < 4; t++) {
        if (q[0] == 0.0f) {
            q[0] = q[1]; q[1] = q[2]; q[2] = q[3]; q[3] = q[4]; q[4] = 0.0f;
            sft++;
        }
    }
    return sft;
}

// ---------------------------------------------------------------------------
// Scatter: per node, <=5 row-v4 REDs + (P=.5) column T-v4 + (P~.125) corner
// (unchanged — measured at the REDG request floor, 5.125 req/node vs 5.06 bound)
// ---------------------------------------------------------------------------
__global__ void __launch_bounds__(256) scatter_kernel(
    const float* __restrict__ pos,
    const float* __restrict__ sxs,
    const float* __restrict__ sys,
    int n)
{
    int i = blockIdx.x * blockDim.x + threadIdx.x;
    if (i >= n) return;

    float x  = pos[i];
    float y  = pos[n + i];
    float sx = sxs[i];
    float sy = sys[i];

    int sx0 = min(max((int)floorf(x - 2.0f), 0), NBX - KK);
    int sy0 = min(max((int)floorf(y - 2.0f), 0), NBY - KK);

    float px[KK], py[KK];
    pot5(x, sx, sx0, px);
    pot5(y, sy, sy0, py);

    // strip y window; q[0..3] = v4 lanes; q[4] = leftover 5th column (0 if width<5)
    float q[KK] = {py[0], py[1], py[2], py[3], py[4]};
    int ys = sy0 + strip5(q);
    float colv = q[4];                 // nonzero only when shift==0 && width==5
    float* Mk = g_M[ys & 3];
    int ycol = (ys & ~3) + 4;          // aligned offset inside copy (ys&3)

#pragma unroll
    for (int r = 0; r < KK; r++) {
        float vx = px[r];
        if (vx != 0.0f)
            red_add_v4(Mk + (sx0 + r) * MS + ycol,
                       vx * q[0], vx * q[1], vx * q[2], vx * q[3]);
    }

    if (colv != 0.0f) {                // 5th column at logical y = sy0+4
        float c[KK] = {px[0], px[1], px[2], px[3], px[4]};
        int xs = sx0 + strip5(c);
        float corner = c[4];           // nonzero only when shift==0 && width==5
        float* Tk = g_T[xs & 3];
        red_add_v4(Tk + (sy0 + 4) * MS + (xs & ~3) + 4,
                   colv * c[0], colv * c[1], colv * c[2], colv * c[3]);
        if (corner != 0.0f)            // corner (sx0+4, sy0+4)
            red_add_f(&g_M[0][(sx0 + 4) * MS + (sy0 + 4) + 4], corner * colv);
    }
}

// ---------------------------------------------------------------------------
// Finish (R11 body + PDL): launched with programmatic stream serialization.
// Blocks start while scatter drains, do all index setup, then wait on the
// grid dependency (scatter completion => all REDs visible) before loading.
// 256 blocks x 1024 threads, 32x32 tile, all accesses 32-wide coalesced.
// ---------------------------------------------------------------------------
__global__ void __launch_bounds__(1024) finish_kernel(
    const float* __restrict__ initial,
    float* __restrict__ out)
{
    __shared__ float ts[32][33];       // stride 33: conflict-free both ways
    __shared__ float sd[32];

    int b    = blockIdx.x;
    int X0   = (b & 15) << 5;
    int Y0   = (b >> 4) << 5;
    int tid  = threadIdx.x;
    int lane = tid & 31;
    int row  = tid >> 5;               // 0..31 (warp id = local row)

    // Precompute every address before the dependency wait (overlapped prologue)
    int ygT = Y0 + row;                // T-space: coalesced along x (lane)
    int xgM = X0 + row;                // M-space: coalesced along y (lane)
    int ygM = Y0 + lane;
    int tBase = ygT * MS + X0 + lane;  // + (4-k) per copy
    int mBase = xgM * MS + ygM;        // + (4-k) per copy
    int iIdx  = xgM * NBY + ygM;

#if __CUDA_ARCH__ >= 900
    cudaGridDependencySynchronize();   // wait for scatter's completion signal
#endif

    // ---- Issue ALL independent global loads first (9-deep MLP) ----
    float t0 = g_T[0][tBase + 4];
    float t1 = g_T[1][tBase + 3];
    float t2 = g_T[2][tBase + 2];
    float t3 = g_T[3][tBase + 1];
    float m0 = g_M[0][mBase + 4];
    float m1 = g_M[1][mBase + 3];
    float m2 = g_M[2][mBase + 2];
    float m3 = g_M[3][mBase + 1];
    float i0 = initial[iIdx];

    // ---- T fold -> smem transpose ----
    ts[row][lane] = t0 + t1 + t2 + t3;
    __syncthreads();

    // ---- per-cell density + cost ----
    float v = i0 + m0 + m1 + m2 + m3 + ts[lane][row];
    float d = v - TARGET_AREA;
    float acc = d * d;

    // ---- zero own region (plain streaming stores, 32-wide) ----
#pragma unroll
    for (int k = 0; k < 4; k++)
        g_T[k][tBase + 4 - k] = 0.0f;
#pragma unroll
    for (int k = 0; k < 4; k++)
        g_M[k][mBase + 4 - k] = 0.0f;

    // ---- block reduce (32 warps) + ticketed final write / state reset ----
#pragma unroll
    for (int off = 16; off > 0; off >>= 1)
        acc += __shfl_xor_sync(0xFFFFFFFF, acc, off);
    if (lane == 0) sd[row] = acc;
    __syncthreads();
    if (tid < 32) {
        float v2 = sd[tid];
#pragma unroll
        for (int off = 16; off > 0; off >>= 1)
            v2 += __shfl_xor_sync(0xFFFFFFFF, v2, off);
        if (tid == 0) {
            atomicAdd(&g_sum, v2);
            __threadfence();
            int t = atomicAdd(&g_done, 1);
            if (t == (int)gridDim.x - 1) {
                out[0] = g_sum;
                g_sum  = 0.0f;         // restore invariants for next replay
                g_done = 0;
            }
        }
    }
}

// ---------------------------------------------------------------------------
extern "C" void kernel_launch(void* const* d_in, const int* in_sizes, int n_in,
                              void* d_out, int out_size) {
    const float* pos = (const float*)d_in[0];
    const float* sx  = (const float*)d_in[1];
    const float* sy  = (const float*)d_in[2];
    // d_in[3..8]: ax..cy — recomputed analytically; d_in[9..10]: bin centers — analytic
    const float* initial = (const float*)d_in[11];
    float* out = (float*)d_out;

    int n = in_sizes[1];

    scatter_kernel<<<(n + 255) / 256, 256>>>(pos, sx, sy, n);

    // finish: PDL launch — prologue overlaps scatter's tail; waits on the
    // programmatic dependency before touching scatter's output.
    {
        cudaLaunchConfig_t cfg = {};
        cfg.gridDim  = dim3(256, 1, 1);
        cfg.blockDim = dim3(1024, 1, 1);
        cfg.dynamicSmemBytes = 0;
        cfg.stream = 0;
        cudaLaunchAttribute attr[1];
        attr[0].id = cudaLaunchAttributeProgrammaticStreamSerialization;
        attr[0].val.programmaticStreamSerializationAllowed = 1;
        cfg.attrs = attr;
        cfg.numAttrs = 1;
        cudaLaunchKernelEx(&cfg, finish_kernel, initial, out);
    }
}

// round 13
// speedup vs baseline: 1.3067x; 1.0067x over previous
#include <cuda_runtime.h>
#include <cuda_bf16.h>

#define NBX 512
#define NBY 512
#define KK  5
#define TARGET_AREA 0.9f
#define MS  520                     // padded map row stride (floats)
#define MAPSZ (512 * MS + 16)       // max used idx 511*520+515

#define FIN_BLOCKS 128              // one balanced wave; 2 tiles (32x32) per block

// ---- static device scratch (no runtime allocation allowed) ----
// M copies: logical (x,y) stored at idx x*MS + (y - k) + 4   (copy k)
// T copies: logical (x,y) stored at idx y*MS + (x - k) + 4   (copy k, transposed)
__device__ __align__(16) float g_M[4][MAPSZ];
__device__ __align__(16) float g_T[4][MAPSZ];
__device__ float g_sum;             // reset by finish's last block
__device__ int   g_done;

__device__ __forceinline__ void red_add_v4(float* a, float v0, float v1, float v2, float v3) {
    asm volatile("red.global.add.v4.f32 [%0], {%1, %2, %3, %4};"
                 :: "l"(a), "f"(v0), "f"(v1), "f"(v2), "f"(v3) : "memory");
}
__device__ __forceinline__ void red_add_f(float* a, float v) {
    asm volatile("red.global.add.f32 [%0], %1;" :: "l"(a), "f"(v) : "memory");
}

// 5 bell-potential values over window starting at s0 (zeros only at the ends)
__device__ __forceinline__ void pot5(float coord, float s, int s0, float* p) {
    float ctr = coord + 0.5f * s;
    float a   = 4.0f / ((s + 2.0f) * (s + 4.0f));
    float cb  = s * (2.0f / (s + 4.0f));
    float p1  = 0.5f * s + 1.0f;
    float p2  = 0.5f * s + 2.0f;
    float d0  = ctr - ((float)s0 + 0.5f);
#pragma unroll
    for (int k = 0; k < KK; k++) {
        float d = fabsf(d0 - (float)k);
        float v;
        if (d < p1)      v = s * (1.0f - a * d * d);
        else if (d < p2) { float t = d - p2; v = cb * t * t; }
        else             v = 0.0f;
        p[k] = v;
    }
}

// strip leading zeros from q[0..4] (shifting zeros in at the top); returns shift
__device__ __forceinline__ int strip5(float* q) {
    int sft = 0;
#pragma unroll
    for (int t = 0; t < 4; t++) {
        if (q[0] == 0.0f) {
            q[0] = q[1]; q[1] = q[2]; q[2] = q[3]; q[3] = q[4]; q[4] = 0.0f;
            sft++;
        }
    }
    return sft;
}

// ---------------------------------------------------------------------------
// Scatter: per node, <=5 row-v4 REDs + (P=.5) column T-v4 + (P~.125) corner
// (unchanged — at the REDG lane floor: 5.125 lanes/node vs 5.06 covering bound)
// ---------------------------------------------------------------------------
__global__ void __launch_bounds__(256) scatter_kernel(
    const float* __restrict__ pos,
    const float* __restrict__ sxs,
    const float* __restrict__ sys,
    int n)
{
    int i = blockIdx.x * blockDim.x + threadIdx.x;
    if (i >= n) return;

    float x  = pos[i];
    float y  = pos[n + i];
    float sx = sxs[i];
    float sy = sys[i];

    int sx0 = min(max((int)floorf(x - 2.0f), 0), NBX - KK);
    int sy0 = min(max((int)floorf(y - 2.0f), 0), NBY - KK);

    float px[KK], py[KK];
    pot5(x, sx, sx0, px);
    pot5(y, sy, sy0, py);

    // strip y window; q[0..3] = v4 lanes; q[4] = leftover 5th column (0 if width<5)
    float q[KK] = {py[0], py[1], py[2], py[3], py[4]};
    int ys = sy0 + strip5(q);
    float colv = q[4];                 // nonzero only when shift==0 && width==5
    float* Mk = g_M[ys & 3];
    int ycol = (ys & ~3) + 4;          // aligned offset inside copy (ys&3)

#pragma unroll
    for (int r = 0; r < KK; r++) {
        float vx = px[r];
        if (vx != 0.0f)
            red_add_v4(Mk + (sx0 + r) * MS + ycol,
                       vx * q[0], vx * q[1], vx * q[2], vx * q[3]);
    }

    if (colv != 0.0f) {                // 5th column at logical y = sy0+4
        float c[KK] = {px[0], px[1], px[2], px[3], px[4]};
        int xs = sx0 + strip5(c);
        float corner = c[4];           // nonzero only when shift==0 && width==5
        float* Tk = g_T[xs & 3];
        red_add_v4(Tk + (sy0 + 4) * MS + (xs & ~3) + 4,
                   colv * c[0], colv * c[1], colv * c[2], colv * c[3]);
        if (corner != 0.0f)            // corner (sx0+4, sy0+4)
            red_add_f(&g_M[0][(sx0 + 4) * MS + (sy0 + 4) + 4], corner * colv);
    }
}

// ---------------------------------------------------------------------------
// Finish: 128 blocks x 1024 threads — ONE balanced wave, TWO 32x32 tiles per
// block (tiles b and b+128). All 18 global loads (2 x (4T + 4M + initial))
// issue back-to-back before the single barrier (MLP 18). All accesses 32-wide
// coalesced. Zeroing separate, own-region only. PDL prologue overlap kept.
// ---------------------------------------------------------------------------
__global__ void __launch_bounds__(1024) finish_kernel(
    const float* __restrict__ initial,
    float* __restrict__ out)
{
    __shared__ float ts[2][32][33];    // stride 33: conflict-free both ways
    __shared__ float sd[32];

    int b    = blockIdx.x;
    int tid  = threadIdx.x;
    int lane = tid & 31;
    int row  = tid >> 5;               // 0..31 (warp id = local row)

    // Tile coordinates for both tiles (t, t+128)
    int X0a = (b & 15) << 5;
    int Y0a = (b >> 4) << 5;
    int tb  = b + FIN_BLOCKS;
    int X0b = (tb & 15) << 5;
    int Y0b = (tb >> 4) << 5;

    // Precompute all addresses before the dependency wait
    int tBaseA = (Y0a + row) * MS + X0a + lane;
    int mRowA  = X0a + row;
    int mBaseA = mRowA * MS + (Y0a + lane);
    int iIdxA  = mRowA * NBY + (Y0a + lane);

    int tBaseB = (Y0b + row) * MS + X0b + lane;
    int mRowB  = X0b + row;
    int mBaseB = mRowB * MS + (Y0b + lane);
    int iIdxB  = mRowB * NBY + (Y0b + lane);

#if __CUDA_ARCH__ >= 900
    cudaGridDependencySynchronize();   // scatter completion => all REDs visible
#endif

    // ---- Issue ALL 18 independent global loads back-to-back ----
    float a_t0 = g_T[0][tBaseA + 4];
    float a_t1 = g_T[1][tBaseA + 3];
    float a_t2 = g_T[2][tBaseA + 2];
    float a_t3 = g_T[3][tBaseA + 1];
    float b_t0 = g_T[0][tBaseB + 4];
    float b_t1 = g_T[1][tBaseB + 3];
    float b_t2 = g_T[2][tBaseB + 2];
    float b_t3 = g_T[3][tBaseB + 1];
    float a_m0 = g_M[0][mBaseA + 4];
    float a_m1 = g_M[1][mBaseA + 3];
    float a_m2 = g_M[2][mBaseA + 2];
    float a_m3 = g_M[3][mBaseA + 1];
    float b_m0 = g_M[0][mBaseB + 4];
    float b_m1 = g_M[1][mBaseB + 3];
    float b_m2 = g_M[2][mBaseB + 2];
    float b_m3 = g_M[3][mBaseB + 1];
    float a_i0 = initial[iIdxA];
    float b_i0 = initial[iIdxB];

    // ---- T fold -> smem transpose (both tiles) ----
    ts[0][row][lane] = a_t0 + a_t1 + a_t2 + a_t3;
    ts[1][row][lane] = b_t0 + b_t1 + b_t2 + b_t3;
    __syncthreads();

    // ---- per-cell density + cost (both tiles) ----
    float va = a_i0 + a_m0 + a_m1 + a_m2 + a_m3 + ts[0][lane][row];
    float vb = b_i0 + b_m0 + b_m1 + b_m2 + b_m3 + ts[1][lane][row];
    float da = va - TARGET_AREA;
    float db = vb - TARGET_AREA;
    float acc = da * da + db * db;

    // ---- zero own regions (plain streaming stores, 32-wide) ----
#pragma unroll
    for (int k = 0; k < 4; k++) {
        g_T[k][tBaseA + 4 - k] = 0.0f;
        g_T[k][tBaseB + 4 - k] = 0.0f;
    }
#pragma unroll
    for (int k = 0; k < 4; k++) {
        g_M[k][mBaseA + 4 - k] = 0.0f;
        g_M[k][mBaseB + 4 - k] = 0.0f;
    }

    // ---- block reduce (32 warps) + ticketed final write / state reset ----
#pragma unroll
    for (int off = 16; off > 0; off >>= 1)
        acc += __shfl_xor_sync(0xFFFFFFFF, acc, off);
    if (lane == 0) sd[row] = acc;
    __syncthreads();
    if (tid < 32) {
        float v2 = sd[tid];
#pragma unroll
        for (int off = 16; off > 0; off >>= 1)
            v2 += __shfl_xor_sync(0xFFFFFFFF, v2, off);
        if (tid == 0) {
            atomicAdd(&g_sum, v2);
            __threadfence();
            int t = atomicAdd(&g_done, 1);
            if (t == (int)gridDim.x - 1) {
                out[0] = g_sum;
                g_sum  = 0.0f;         // restore invariants for next replay
                g_done = 0;
            }
        }
    }
}

// ---------------------------------------------------------------------------
extern "C" void kernel_launch(void* const* d_in, const int* in_sizes, int n_in,
                              void* d_out, int out_size) {
    const float* pos = (const float*)d_in[0];
    const float* sx  = (const float*)d_in[1];
    const float* sy  = (const float*)d_in[2];
    // d_in[3..8]: ax..cy — recomputed analytically; d_in[9..10]: bin centers — analytic
    const float* initial = (const float*)d_in[11];
    float* out = (float*)d_out;

    int n = in_sizes[1];

    scatter_kernel<<<(n + 255) / 256, 256>>>(pos, sx, sy, n);

    // finish: PDL launch — prologue overlaps scatter's tail; waits on the
    // programmatic dependency before touching scatter's output.
    {
        cudaLaunchConfig_t cfg = {};
        cfg.gridDim  = dim3(FIN_BLOCKS, 1, 1);
        cfg.blockDim = dim3(1024, 1, 1);
        cfg.dynamicSmemBytes = 0;
        cfg.stream = 0;
        cudaLaunchAttribute attr[1];
        attr[0].id = cudaLaunchAttributeProgrammaticStreamSerialization;
        attr[0].val.programmaticStreamSerializationAllowed = 1;
        cfg.attrs = attr;
        cfg.numAttrs = 1;
        cudaLaunchKernelEx(&cfg, finish_kernel, initial, out);
    }
}